// round 5
// baseline (speedup 1.0000x reference)
#include <cuda_runtime.h>
#include <cuda_bf16.h>
#include <math_constants.h>
#include <cstdint>

// ============================================================================
// Problem constants
// ============================================================================
#define D        256
#define MROWS    32768
#define KCODES   8192
#define NTILE    32            // KCODES / 256
#define BM       128
#define BN       128
#define BK       16
#define TM       8
#define TN       8
#define NTHREADS 256

// dist kernel smem geometry
#define SB       40                    // smem row stride in bf16 (80 B, 16B-aligned, conflict-free)
#define TILEB    (128 * SB * 2)        // 10240 B : 128-row tile
#define BTILEB   (256 * SB * 2)        // 20480 B : 256-row tile
#define STAGEB   (2 * TILEB + BTILEB)  // 40960 B per stage
#define NSTAGE   3
#define DIST_SMEM (NSTAGE * STAGEB)    // 122880 B

// ============================================================================
// Device scratch (no cudaMalloc allowed)
// ============================================================================
__device__ float          g_cn[KCODES];
__device__ int            g_idx[MROWS];
__device__ float          g_part[512];
__device__ __nv_bfloat16  g_cbh[KCODES * D];
__device__ __nv_bfloat16  g_zh[MROWS * D];
__device__ __nv_bfloat16  g_zl[MROWS * D];
__device__ float2         g_cv[(size_t)MROWS * NTILE];
__device__ int2           g_ci[(size_t)MROWS * NTILE];

// ============================================================================
// Helpers
// ============================================================================
__device__ __forceinline__ uint32_t smem_to_u32(const void* p) {
    uint32_t a;
    asm("{ .reg .u64 t; cvta.to.shared.u64 t, %1; cvt.u32.u64 %0, t; }"
        : "=r"(a) : "l"(p));
    return a;
}
__device__ __forceinline__ void cp16(uint32_t dst, const void* src) {
    asm volatile("cp.async.cg.shared.global [%0], [%1], 16;"
        :: "r"(dst), "l"(__cvta_generic_to_global(src)) : "memory");
}
__device__ __forceinline__ void ldsm_x4(uint32_t& r0, uint32_t& r1,
                                        uint32_t& r2, uint32_t& r3, uint32_t addr) {
    asm volatile("ldmatrix.sync.aligned.m8n8.x4.shared.b16 {%0,%1,%2,%3}, [%4];"
        : "=r"(r0), "=r"(r1), "=r"(r2), "=r"(r3) : "r"(addr));
}
__device__ __forceinline__ void mma16816(float* c, uint32_t a0, uint32_t a1,
                                         uint32_t a2, uint32_t a3,
                                         uint32_t b0, uint32_t b1) {
    asm volatile("mma.sync.aligned.m16n8k16.row.col.f32.bf16.bf16.f32 "
        "{%0,%1,%2,%3}, {%4,%5,%6,%7}, {%8,%9}, {%0,%1,%2,%3};"
        : "+f"(c[0]), "+f"(c[1]), "+f"(c[2]), "+f"(c[3])
        : "r"(a0), "r"(a1), "r"(a2), "r"(a3), "r"(b0), "r"(b1));
}
__device__ __forceinline__ void top2_merge(float& v0, int& i0, float& v1, int& i1,
                                           float w0, int j0, float w1, int j1) {
    if (w0 < v0) {
        if (v0 < w1) { v1 = v0; i1 = i0; } else { v1 = w1; i1 = j1; }
        v0 = w0; i0 = j0;
    } else if (w0 < v1) { v1 = w0; i1 = j0; }
}

// ============================================================================
// Kernel 1: fused codebook norms + bf16 hi-split (one pass over cb)
// ============================================================================
__global__ __launch_bounds__(256)
void cnsplit_kernel(const float* __restrict__ cb) {
    int row = blockIdx.x * 8 + (threadIdx.x >> 5);
    int lane = threadIdx.x & 31;
    const float4* src = reinterpret_cast<const float4*>(cb + (size_t)row * D);
    __nv_bfloat162* dh = reinterpret_cast<__nv_bfloat162*>(g_cbh + (size_t)row * D);
    float s = 0.f;
#pragma unroll
    for (int p = 0; p < 2; ++p) {
        int q = lane + p * 32;
        float4 v = src[q];
        s += v.x * v.x + v.y * v.y + v.z * v.z + v.w * v.w;
        dh[q * 2 + 0] = __nv_bfloat162(__float2bfloat16(v.x), __float2bfloat16(v.y));
        dh[q * 2 + 1] = __nv_bfloat162(__float2bfloat16(v.z), __float2bfloat16(v.w));
    }
#pragma unroll
    for (int o = 16; o > 0; o >>= 1) s += __shfl_xor_sync(0xffffffffu, s, o);
    if (lane == 0) g_cn[row] = s;
}

// ============================================================================
// Kernel 2: projection z = x W^T + b (exact fp32 SIMT) + bf16 hi/lo split of z
// ============================================================================
__device__ __forceinline__ void load_tile(float dst[BK][BM + 4],
                                          const float* __restrict__ src,
                                          int rowBase, int kt, int tid) {
#pragma unroll
    for (int p = 0; p < 2; ++p) {
        int id = tid + p * NTHREADS;
        int r = id >> 2, c4 = id & 3;
        float4 v = *reinterpret_cast<const float4*>(
            src + (size_t)(rowBase + r) * D + kt * BK + c4 * 4);
        dst[c4 * 4 + 0][r] = v.x;
        dst[c4 * 4 + 1][r] = v.y;
        dst[c4 * 4 + 2][r] = v.z;
        dst[c4 * 4 + 3][r] = v.w;
    }
}

__global__ __launch_bounds__(NTHREADS, 2)
void proj_kernel(const float* __restrict__ x, const float* __restrict__ W,
                 const float* __restrict__ b, float* __restrict__ z) {
    __shared__ float Xs[BK][BM + 4];
    __shared__ float Ws[BK][BN + 4];

    int tid = threadIdx.x;
    int tx = tid & 15, ty = tid >> 4;
    int rowBase = blockIdx.x * BM;
    int colBase = blockIdx.y * BN;

    float acc[TM][TN];
#pragma unroll
    for (int i = 0; i < TM; ++i)
#pragma unroll
        for (int j = 0; j < TN; ++j) acc[i][j] = 0.f;

    for (int kt = 0; kt < D / BK; ++kt) {
        load_tile(Xs, x, rowBase, kt, tid);
        load_tile(Ws, W, colBase, kt, tid);
        __syncthreads();
#pragma unroll
        for (int kk = 0; kk < BK; ++kk) {
            float a[TM], bb[TN];
#pragma unroll
            for (int i = 0; i < TM; ++i) a[i] = Xs[kk][ty * TM + i];
#pragma unroll
            for (int j = 0; j < TN; ++j) bb[j] = Ws[kk][tx * TN + j];
#pragma unroll
            for (int i = 0; i < TM; ++i)
#pragma unroll
                for (int j = 0; j < TN; ++j)
                    acc[i][j] = fmaf(a[i], bb[j], acc[i][j]);
        }
        __syncthreads();
    }

    int col0 = colBase + tx * TN;
#pragma unroll
    for (int i = 0; i < TM; ++i) {
        int row = rowBase + ty * TM + i;
        float* zrow = z + (size_t)row * D + col0;
        __nv_bfloat162* hrow = reinterpret_cast<__nv_bfloat162*>(g_zh + (size_t)row * D) + (col0 >> 1);
        __nv_bfloat162* lrow = reinterpret_cast<__nv_bfloat162*>(g_zl + (size_t)row * D) + (col0 >> 1);
#pragma unroll
        for (int j4 = 0; j4 < TN / 4; ++j4) {
            float4 v;
            v.x = acc[i][j4 * 4 + 0] + b[col0 + j4 * 4 + 0];
            v.y = acc[i][j4 * 4 + 1] + b[col0 + j4 * 4 + 1];
            v.z = acc[i][j4 * 4 + 2] + b[col0 + j4 * 4 + 2];
            v.w = acc[i][j4 * 4 + 3] + b[col0 + j4 * 4 + 3];
            *reinterpret_cast<float4*>(zrow + j4 * 4) = v;
            __nv_bfloat16 h0 = __float2bfloat16(v.x), h1 = __float2bfloat16(v.y);
            __nv_bfloat16 h2 = __float2bfloat16(v.z), h3 = __float2bfloat16(v.w);
            hrow[j4 * 2 + 0] = __nv_bfloat162(h0, h1);
            hrow[j4 * 2 + 1] = __nv_bfloat162(h2, h3);
            lrow[j4 * 2 + 0] = __nv_bfloat162(__float2bfloat16(v.x - __bfloat162float(h0)),
                                              __float2bfloat16(v.y - __bfloat162float(h1)));
            lrow[j4 * 2 + 1] = __nv_bfloat162(__float2bfloat16(v.z - __bfloat162float(h2)),
                                              __float2bfloat16(v.w - __bfloat162float(h3)));
        }
    }
}

// ============================================================================
// Kernel 3: distance GEMM on HMMA, 2-term split (dot = zh.eh + zl.eh = z.eh).
// CTA tile 128 rows x 256 codes, 8 warps (2x4), warp tile 64x64.
// BK=32, 3-stage cp.async ring, 1 barrier per k-chunk (8 iterations).
// Per-row top-2 per 256-code tile -> candidates for exact rescore.
// ============================================================================
__global__ __launch_bounds__(256, 1)
void dist_mma_kernel(int Kcodes) {
    extern __shared__ __align__(16) char smem[];
    const uint32_t smBase = smem_to_u32(smem);

    const int tid = threadIdx.x, lane = tid & 31, wid = tid >> 5;
    const int wm = wid >> 2, wn = wid & 3;        // 2 x 4 warp grid
    const int rowBase = blockIdx.x * 128;
    const int codeBase = blockIdx.y * 256;

    // ldmatrix lane addressing
    const int q = lane >> 3, i8 = lane & 7;
    const uint32_t aOff = (uint32_t)(((wm * 64 + (q & 1) * 8 + i8) * SB + (q >> 1) * 8) * 2);
    const uint32_t bOff = (uint32_t)(((wn * 64 + (q >> 1) * 8 + i8) * SB + (q & 1) * 8) * 2);

    float acc[4][8][4];
#pragma unroll
    for (int mt = 0; mt < 4; ++mt)
#pragma unroll
        for (int nt = 0; nt < 8; ++nt)
#pragma unroll
            for (int e = 0; e < 4; ++e) acc[mt][nt][e] = 0.f;

    // stage k-chunk kt (32 k) into ring buffer 'buf':
    // 2048 x 16B chunks: zh(512), zl(512), eh(1024); 8 per thread
    auto stage = [&](int buf, int kt) {
        uint32_t base = smBase + buf * STAGEB;
        int kc = kt * 32;
#pragma unroll
        for (int i = 0; i < 8; ++i) {
            int c = tid + i * 256;
            if (c < 1024) {
                int hf = c & 3;
                int r = (c >> 2) & 127;
                const __nv_bfloat16* src = (c < 512) ? g_zh : g_zl;
                uint32_t toff = (c < 512) ? 0u : (uint32_t)TILEB;
                cp16(base + toff + (uint32_t)(r * (SB * 2) + hf * 16),
                     src + (size_t)(rowBase + r) * D + kc + hf * 8);
            } else {
                int cc = c - 1024;
                int hf = cc & 3;
                int r = cc >> 2;     // 0..255
                cp16(base + 2 * TILEB + (uint32_t)(r * (SB * 2) + hf * 16),
                     g_cbh + (size_t)(codeBase + r) * D + kc + hf * 8);
            }
        }
        asm volatile("cp.async.commit_group;" ::: "memory");
    };

    stage(0, 0);
    stage(1, 1);
    for (int kt = 0; kt < 8; ++kt) {
        int buf = kt - (kt >= 3 ? 3 : 0) - (kt >= 6 ? 3 : 0);   // kt % 3
        if (kt < 7) asm volatile("cp.async.wait_group 1;" ::: "memory");
        else        asm volatile("cp.async.wait_group 0;" ::: "memory");
        __syncthreads();
        if (kt < 6) stage(kt + 2 - (kt + 2 >= 3 ? 3 : 0) - (kt + 2 >= 6 ? 3 : 0), kt + 2);

        uint32_t tb = smBase + buf * STAGEB;
#pragma unroll
        for (int kh = 0; kh < 2; ++kh) {
            uint32_t ah[4][4], al[4][4], bfr[8][2];
#pragma unroll
            for (int mt = 0; mt < 4; ++mt)
                ldsm_x4(ah[mt][0], ah[mt][1], ah[mt][2], ah[mt][3],
                        tb + aOff + (uint32_t)(mt * 16 * SB * 2 + kh * 32));
#pragma unroll
            for (int mt = 0; mt < 4; ++mt)
                ldsm_x4(al[mt][0], al[mt][1], al[mt][2], al[mt][3],
                        tb + TILEB + aOff + (uint32_t)(mt * 16 * SB * 2 + kh * 32));
#pragma unroll
            for (int nt2 = 0; nt2 < 4; ++nt2) {
                uint32_t r0, r1, r2, r3;
                ldsm_x4(r0, r1, r2, r3,
                        tb + 2 * TILEB + bOff + (uint32_t)(nt2 * 16 * SB * 2 + kh * 32));
                bfr[nt2 * 2 + 0][0] = r0; bfr[nt2 * 2 + 0][1] = r1;
                bfr[nt2 * 2 + 1][0] = r2; bfr[nt2 * 2 + 1][1] = r3;
            }
#pragma unroll
            for (int mt = 0; mt < 4; ++mt)
#pragma unroll
                for (int nt = 0; nt < 8; ++nt)
                    mma16816(acc[mt][nt], ah[mt][0], ah[mt][1], ah[mt][2], ah[mt][3],
                             bfr[nt][0], bfr[nt][1]);
#pragma unroll
            for (int mt = 0; mt < 4; ++mt)
#pragma unroll
                for (int nt = 0; nt < 8; ++nt)
                    mma16816(acc[mt][nt], al[mt][0], al[mt][1], al[mt][2], al[mt][3],
                             bfr[nt][0], bfr[nt][1]);
        }
    }

    // ---- epilogue: d = cn - 2*dot, per-row top-2 over this CTA's 256 codes ----
    __syncthreads();                      // mainloop smem dead; alias as red[]
    float4 (*red)[4] = reinterpret_cast<float4(*)[4]>(smem);

    const int g = lane >> 2;
    const int cb0 = codeBase + wn * 64 + (lane & 3) * 2;
    float cn8[8][2];
#pragma unroll
    for (int nt = 0; nt < 8; ++nt) {
        cn8[nt][0] = __ldg(&g_cn[cb0 + nt * 8 + 0]);
        cn8[nt][1] = __ldg(&g_cn[cb0 + nt * 8 + 1]);
    }
#pragma unroll
    for (int mt = 0; mt < 4; ++mt)
#pragma unroll
        for (int h = 0; h < 2; ++h) {
            float v0 = CUDART_INF_F, v1 = CUDART_INF_F;
            int i0 = 0, i1 = 0;
#pragma unroll
            for (int nt = 0; nt < 8; ++nt)
#pragma unroll
                for (int e = 0; e < 2; ++e) {
                    float dd = fmaf(-2.f, acc[mt][nt][h * 2 + e], cn8[nt][e]);
                    int code = cb0 + nt * 8 + e;
                    if (dd < v0) { v1 = v0; i1 = i0; v0 = dd; i0 = code; }
                    else if (dd < v1) { v1 = dd; i1 = code; }
                }
#pragma unroll
            for (int off = 1; off <= 2; off <<= 1) {
                float w0 = __shfl_xor_sync(0xffffffffu, v0, off);
                float w1 = __shfl_xor_sync(0xffffffffu, v1, off);
                int j0 = __shfl_xor_sync(0xffffffffu, i0, off);
                int j1 = __shfl_xor_sync(0xffffffffu, i1, off);
                top2_merge(v0, i0, v1, i1, w0, j0, w1, j1);
            }
            if ((lane & 3) == 0)
                red[wm * 64 + mt * 16 + h * 8 + g][wn] =
                    make_float4(v0, __int_as_float(i0), v1, __int_as_float(i1));
        }
    __syncthreads();

    if (tid < 128) {
        float v0 = CUDART_INF_F, v1 = CUDART_INF_F;
        int i0 = 0, i1 = 0;
#pragma unroll
        for (int w = 0; w < 4; ++w) {
            float4 p = red[tid][w];
            top2_merge(v0, i0, v1, i1, p.x, __float_as_int(p.y), p.z, __float_as_int(p.w));
        }
        size_t slot = (size_t)(rowBase + tid) * gridDim.y + blockIdx.y;
        g_cv[slot] = make_float2(v0, v1);
        g_ci[slot] = make_int2(i0, i1);
    }
}

// ============================================================================
// Kernel 4: per-row reduce (approx top-4 of 2*NT candidates) + exact fp32
// rescore with d = cn - 2*z.e. One warp per row. NT <= 32.
// ============================================================================
__global__ __launch_bounds__(256)
void reduce_rescore_kernel(const float* __restrict__ z,
                           const float* __restrict__ cb, int NT) {
    int row = blockIdx.x * 8 + (threadIdx.x >> 5);
    int lane = threadIdx.x & 31;

    float v[2] = { CUDART_INF_F, CUDART_INF_F };
    int ix[2] = { -1, -1 };
    if (lane < NT) {
        float2 cv = g_cv[(size_t)row * NT + lane];
        int2 ci = g_ci[(size_t)row * NT + lane];
        v[0] = cv.x; ix[0] = ci.x;
        v[1] = cv.y; ix[1] = ci.y;
    }

    // pass 1: global approx top-2 (per-slot pair already sorted)
    float a0 = v[0], a1 = v[1];
    int b0 = ix[0], b1 = ix[1];
#pragma unroll
    for (int off = 16; off > 0; off >>= 1) {
        float w0 = __shfl_xor_sync(0xffffffffu, a0, off);
        float w1 = __shfl_xor_sync(0xffffffffu, a1, off);
        int j0 = __shfl_xor_sync(0xffffffffu, b0, off);
        int j1 = __shfl_xor_sync(0xffffffffu, b1, off);
        top2_merge(a0, b0, a1, b1, w0, j0, w1, j1);
    }
    int t0 = b0, t1 = b1;

    // pass 2: approx ranks 3-4 (exclude t0, t1)
    float c0 = CUDART_INF_F, c1 = CUDART_INF_F;
    int d0 = -1, d1 = -1;
#pragma unroll
    for (int k = 0; k < 2; ++k) {
        if (ix[k] != t0 && ix[k] != t1 && ix[k] >= 0) {
            if (v[k] < c0) { c1 = c0; d1 = d0; c0 = v[k]; d0 = ix[k]; }
            else if (v[k] < c1) { c1 = v[k]; d1 = ix[k]; }
        }
    }
#pragma unroll
    for (int off = 16; off > 0; off >>= 1) {
        float w0 = __shfl_xor_sync(0xffffffffu, c0, off);
        float w1 = __shfl_xor_sync(0xffffffffu, c1, off);
        int j0 = __shfl_xor_sync(0xffffffffu, d0, off);
        int j1 = __shfl_xor_sync(0xffffffffu, d1, off);
        top2_merge(c0, d0, c1, d1, w0, j0, w1, j1);
    }

    int jj[4] = { t0, t1, (d0 >= 0 ? d0 : t0), (d1 >= 0 ? d1 : t1) };

    // exact fp32 rescore: d_j = cn[j] - 2 * z.e_j
    const float4* zr = reinterpret_cast<const float4*>(z + (size_t)row * D);
    const float4* e0 = reinterpret_cast<const float4*>(cb + (size_t)jj[0] * D);
    const float4* e1 = reinterpret_cast<const float4*>(cb + (size_t)jj[1] * D);
    const float4* e2 = reinterpret_cast<const float4*>(cb + (size_t)jj[2] * D);
    const float4* e3 = reinterpret_cast<const float4*>(cb + (size_t)jj[3] * D);
    float s0 = 0.f, s1 = 0.f, s2 = 0.f, s3 = 0.f;
#pragma unroll
    for (int p = 0; p < 2; ++p) {
        int qd = lane + p * 32;
        float4 zv = zr[qd];
        float4 a = e0[qd];
        s0 = fmaf(zv.x, a.x, s0); s0 = fmaf(zv.y, a.y, s0);
        s0 = fmaf(zv.z, a.z, s0); s0 = fmaf(zv.w, a.w, s0);
        a = e1[qd];
        s1 = fmaf(zv.x, a.x, s1); s1 = fmaf(zv.y, a.y, s1);
        s1 = fmaf(zv.z, a.z, s1); s1 = fmaf(zv.w, a.w, s1);
        a = e2[qd];
        s2 = fmaf(zv.x, a.x, s2); s2 = fmaf(zv.y, a.y, s2);
        s2 = fmaf(zv.z, a.z, s2); s2 = fmaf(zv.w, a.w, s2);
        a = e3[qd];
        s3 = fmaf(zv.x, a.x, s3); s3 = fmaf(zv.y, a.y, s3);
        s3 = fmaf(zv.z, a.z, s3); s3 = fmaf(zv.w, a.w, s3);
    }
#pragma unroll
    for (int off = 16; off > 0; off >>= 1) {
        s0 += __shfl_xor_sync(0xffffffffu, s0, off);
        s1 += __shfl_xor_sync(0xffffffffu, s1, off);
        s2 += __shfl_xor_sync(0xffffffffu, s2, off);
        s3 += __shfl_xor_sync(0xffffffffu, s3, off);
    }
    if (lane == 0) {
        float dj[4];
        dj[0] = g_cn[jj[0]] - 2.f * s0;
        dj[1] = g_cn[jj[1]] - 2.f * s1;
        dj[2] = g_cn[jj[2]] - 2.f * s2;
        dj[3] = g_cn[jj[3]] - 2.f * s3;
        float best = dj[0]; int bi = jj[0];
#pragma unroll
        for (int k = 1; k < 4; ++k)
            if (dj[k] < best || (dj[k] == best && jj[k] < bi)) { best = dj[k]; bi = jj[k]; }
        g_idx[row] = bi;
    }
}

// ============================================================================
// Kernel 5: gather + straight-through recon + loss partials
// ============================================================================
__global__ void gather_loss_kernel(float* __restrict__ out,
                                   const float* __restrict__ cb,
                                   int total4) {
    int t = blockIdx.x * blockDim.x + threadIdx.x;
    int stride = gridDim.x * blockDim.x;
    float s = 0.f;
    for (int e4 = t; e4 < total4; e4 += stride) {
        int n = e4 >> 6;
        int c4 = e4 & 63;
        int k = g_idx[n];
        float4 qv = reinterpret_cast<const float4*>(cb + (size_t)k * D)[c4];
        float4 zv = reinterpret_cast<float4*>(out)[e4];
        reinterpret_cast<float4*>(out)[e4] = qv;   // z + (q - z) == q
        float dx = zv.x - qv.x, dy = zv.y - qv.y, dz = zv.z - qv.z, dw = zv.w - qv.w;
        s += dx * dx + dy * dy + dz * dz + dw * dw;
    }
    __shared__ float sr[256];
    sr[threadIdx.x] = s;
    __syncthreads();
    for (int st = 128; st > 0; st >>= 1) {
        if (threadIdx.x < st) sr[threadIdx.x] += sr[threadIdx.x + st];
        __syncthreads();
    }
    if (threadIdx.x == 0) g_part[blockIdx.x] = sr[0];
}

// ============================================================================
// Kernel 6: finalize losses
// ============================================================================
__global__ void finalize_kernel(float* __restrict__ out, int out_size,
                                float inv_count) {
    __shared__ float sr[512];
    int t = threadIdx.x;
    sr[t] = g_part[t];
    __syncthreads();
    for (int st = 256; st > 0; st >>= 1) {
        if (t < st) sr[t] += sr[t + st];
        __syncthreads();
    }
    if (t == 0) {
        float m = sr[0] * inv_count;
        out[out_size - 2] = m;
        out[out_size - 1] = m;
    }
}

// ============================================================================
extern "C" void kernel_launch(void* const* d_in, const int* in_sizes, int n_in,
                              void* d_out, int out_size) {
    const float* x  = (const float*)d_in[0];
    const float* W  = (const float*)d_in[1];
    const float* b  = (const float*)d_in[2];
    const float* cb = (const float*)d_in[3];

    int M      = in_sizes[0] / D;   // 32768
    int Kcodes = in_sizes[3] / D;   // 8192
    int NT     = Kcodes / 256;      // 32
    float* out = (float*)d_out;

    // allow 120KB dynamic smem for the dist kernel (host-side attr, capture-safe)
    cudaFuncSetAttribute(dist_mma_kernel,
                         cudaFuncAttributeMaxDynamicSharedMemorySize, DIST_SMEM);

    // 1. fused codebook norms + bf16 hi split
    cnsplit_kernel<<<Kcodes / 8, 256>>>(cb);

    // 2. projection (exact fp32 z into out, plus bf16 hi/lo of z)
    dim3 pg(M / BM, D / BN);
    proj_kernel<<<pg, NTHREADS>>>(x, W, b, out);

    // 3. HMMA distance GEMM (2-term, 128x256 tiles), per-tile top-2 candidates
    dist_mma_kernel<<<dim3(M / 128, NT), 256, DIST_SMEM>>>(Kcodes);

    // 4. reduce candidates + exact fp32 rescore of top-4
    reduce_rescore_kernel<<<M / 8, 256>>>(out, cb, NT);

    // 5. gather + losses
    gather_loss_kernel<<<512, 256>>>(out, cb, (M * D) / 4);

    // 6. finalize
    finalize_kernel<<<1, 512>>>(out, out_size, 1.0f / (float)(M * D));
}

// round 6
// speedup vs baseline: 1.3301x; 1.3301x over previous
#include <cuda_runtime.h>
#include <cuda_bf16.h>
#include <math_constants.h>
#include <cstdint>

// ============================================================================
// Problem constants
// ============================================================================
#define D        256
#define MROWS    32768
#define KCODES   8192
#define NTILE    64            // KCODES / 128
#define BM       128
#define BN       128
#define BK       16
#define TM       8
#define TN       8
#define NTHREADS 256

// dist kernel smem geometry (BK = 32)
#define SB       40                    // smem row stride in bf16 (80 B, conflict-free)
#define TILEB    (128 * SB * 2)        // 10240 B per 128x32 tile
#define STAGEB   (3 * TILEB)           // zh + zl + eh = 30720 B per stage
#define NSTAGE   3
#define DIST_SMEM (NSTAGE * STAGEB)    // 92160 B -> 2 CTAs/SM

// ============================================================================
// Device scratch (no cudaMalloc allowed)
// ============================================================================
__device__ float          g_cn[KCODES];
__device__ int            g_idx[MROWS];
__device__ float          g_part[512];
__device__ __nv_bfloat16  g_cbh[KCODES * D];
__device__ __nv_bfloat16  g_zh[MROWS * D];
__device__ __nv_bfloat16  g_zl[MROWS * D];
__device__ float2         g_cv[(size_t)MROWS * NTILE];
__device__ int2           g_ci[(size_t)MROWS * NTILE];

// ============================================================================
// Helpers
// ============================================================================
__device__ __forceinline__ uint32_t smem_to_u32(const void* p) {
    uint32_t a;
    asm("{ .reg .u64 t; cvta.to.shared.u64 t, %1; cvt.u32.u64 %0, t; }"
        : "=r"(a) : "l"(p));
    return a;
}
__device__ __forceinline__ void cp16(uint32_t dst, const void* src) {
    asm volatile("cp.async.cg.shared.global [%0], [%1], 16;"
        :: "r"(dst), "l"(__cvta_generic_to_global(src)) : "memory");
}
__device__ __forceinline__ void ldsm_x4(uint32_t& r0, uint32_t& r1,
                                        uint32_t& r2, uint32_t& r3, uint32_t addr) {
    asm volatile("ldmatrix.sync.aligned.m8n8.x4.shared.b16 {%0,%1,%2,%3}, [%4];"
        : "=r"(r0), "=r"(r1), "=r"(r2), "=r"(r3) : "r"(addr));
}
__device__ __forceinline__ void mma16816(float* c, uint32_t a0, uint32_t a1,
                                         uint32_t a2, uint32_t a3,
                                         uint32_t b0, uint32_t b1) {
    asm volatile("mma.sync.aligned.m16n8k16.row.col.f32.bf16.bf16.f32 "
        "{%0,%1,%2,%3}, {%4,%5,%6,%7}, {%8,%9}, {%0,%1,%2,%3};"
        : "+f"(c[0]), "+f"(c[1]), "+f"(c[2]), "+f"(c[3])
        : "r"(a0), "r"(a1), "r"(a2), "r"(a3), "r"(b0), "r"(b1));
}
__device__ __forceinline__ void top2_merge(float& v0, int& i0, float& v1, int& i1,
                                           float w0, int j0, float w1, int j1) {
    if (w0 < v0) {
        if (v0 < w1) { v1 = v0; i1 = i0; } else { v1 = w1; i1 = j1; }
        v0 = w0; i0 = j0;
    } else if (w0 < v1) { v1 = w0; i1 = j0; }
}

// ============================================================================
// Kernel 1: fused codebook norms + bf16 hi-split (one pass over cb)
// ============================================================================
__global__ __launch_bounds__(256)
void cnsplit_kernel(const float* __restrict__ cb) {
    int row = blockIdx.x * 8 + (threadIdx.x >> 5);
    int lane = threadIdx.x & 31;
    const float4* src = reinterpret_cast<const float4*>(cb + (size_t)row * D);
    __nv_bfloat162* dh = reinterpret_cast<__nv_bfloat162*>(g_cbh + (size_t)row * D);
    float s = 0.f;
#pragma unroll
    for (int p = 0; p < 2; ++p) {
        int q = lane + p * 32;
        float4 v = src[q];
        s += v.x * v.x + v.y * v.y + v.z * v.z + v.w * v.w;
        dh[q * 2 + 0] = __nv_bfloat162(__float2bfloat16(v.x), __float2bfloat16(v.y));
        dh[q * 2 + 1] = __nv_bfloat162(__float2bfloat16(v.z), __float2bfloat16(v.w));
    }
#pragma unroll
    for (int o = 16; o > 0; o >>= 1) s += __shfl_xor_sync(0xffffffffu, s, o);
    if (lane == 0) g_cn[row] = s;
}

// ============================================================================
// Kernel 2: projection z = x W^T + b (exact fp32 SIMT) + bf16 hi/lo split of z
// ============================================================================
__device__ __forceinline__ void load_tile(float dst[BK][BM + 4],
                                          const float* __restrict__ src,
                                          int rowBase, int kt, int tid) {
#pragma unroll
    for (int p = 0; p < 2; ++p) {
        int id = tid + p * NTHREADS;
        int r = id >> 2, c4 = id & 3;
        float4 v = *reinterpret_cast<const float4*>(
            src + (size_t)(rowBase + r) * D + kt * BK + c4 * 4);
        dst[c4 * 4 + 0][r] = v.x;
        dst[c4 * 4 + 1][r] = v.y;
        dst[c4 * 4 + 2][r] = v.z;
        dst[c4 * 4 + 3][r] = v.w;
    }
}

__global__ __launch_bounds__(NTHREADS, 2)
void proj_kernel(const float* __restrict__ x, const float* __restrict__ W,
                 const float* __restrict__ b, float* __restrict__ z) {
    __shared__ float Xs[BK][BM + 4];
    __shared__ float Ws[BK][BN + 4];

    int tid = threadIdx.x;
    int tx = tid & 15, ty = tid >> 4;
    int rowBase = blockIdx.x * BM;
    int colBase = blockIdx.y * BN;

    float acc[TM][TN];
#pragma unroll
    for (int i = 0; i < TM; ++i)
#pragma unroll
        for (int j = 0; j < TN; ++j) acc[i][j] = 0.f;

    for (int kt = 0; kt < D / BK; ++kt) {
        load_tile(Xs, x, rowBase, kt, tid);
        load_tile(Ws, W, colBase, kt, tid);
        __syncthreads();
#pragma unroll
        for (int kk = 0; kk < BK; ++kk) {
            float a[TM], bb[TN];
#pragma unroll
            for (int i = 0; i < TM; ++i) a[i] = Xs[kk][ty * TM + i];
#pragma unroll
            for (int j = 0; j < TN; ++j) bb[j] = Ws[kk][tx * TN + j];
#pragma unroll
            for (int i = 0; i < TM; ++i)
#pragma unroll
                for (int j = 0; j < TN; ++j)
                    acc[i][j] = fmaf(a[i], bb[j], acc[i][j]);
        }
        __syncthreads();
    }

    int col0 = colBase + tx * TN;
#pragma unroll
    for (int i = 0; i < TM; ++i) {
        int row = rowBase + ty * TM + i;
        float* zrow = z + (size_t)row * D + col0;
        __nv_bfloat162* hrow = reinterpret_cast<__nv_bfloat162*>(g_zh + (size_t)row * D) + (col0 >> 1);
        __nv_bfloat162* lrow = reinterpret_cast<__nv_bfloat162*>(g_zl + (size_t)row * D) + (col0 >> 1);
#pragma unroll
        for (int j4 = 0; j4 < TN / 4; ++j4) {
            float4 v;
            v.x = acc[i][j4 * 4 + 0] + b[col0 + j4 * 4 + 0];
            v.y = acc[i][j4 * 4 + 1] + b[col0 + j4 * 4 + 1];
            v.z = acc[i][j4 * 4 + 2] + b[col0 + j4 * 4 + 2];
            v.w = acc[i][j4 * 4 + 3] + b[col0 + j4 * 4 + 3];
            *reinterpret_cast<float4*>(zrow + j4 * 4) = v;
            __nv_bfloat16 h0 = __float2bfloat16(v.x), h1 = __float2bfloat16(v.y);
            __nv_bfloat16 h2 = __float2bfloat16(v.z), h3 = __float2bfloat16(v.w);
            hrow[j4 * 2 + 0] = __nv_bfloat162(h0, h1);
            hrow[j4 * 2 + 1] = __nv_bfloat162(h2, h3);
            lrow[j4 * 2 + 0] = __nv_bfloat162(__float2bfloat16(v.x - __bfloat162float(h0)),
                                              __float2bfloat16(v.y - __bfloat162float(h1)));
            lrow[j4 * 2 + 1] = __nv_bfloat162(__float2bfloat16(v.z - __bfloat162float(h2)),
                                              __float2bfloat16(v.w - __bfloat162float(h3)));
        }
    }
}

// ============================================================================
// Kernel 3: distance GEMM on HMMA, 2-term split (dot = zh.eh + zl.eh = z.eh).
// CTA tile 128 rows x 128 codes, 8 warps (2x4), warp tile 64x32 -> 2 CTAs/SM.
// BK=32, 3-stage cp.async ring, 8 iterations, 1 barrier each.
// Per-row top-2 per 128-code tile -> candidates for exact rescore.
// ============================================================================
__global__ __launch_bounds__(256, 2)
void dist_mma_kernel(int Kcodes) {
    extern __shared__ __align__(16) char smem[];
    const uint32_t smBase = smem_to_u32(smem);

    const int tid = threadIdx.x, lane = tid & 31, wid = tid >> 5;
    const int wm = wid >> 2, wn = wid & 3;        // 2 x 4 warp grid
    const int rowBase = blockIdx.x * 128;
    const int codeBase = blockIdx.y * 128;

    // ldmatrix lane addressing (within a tile)
    const int q = lane >> 3, i8 = lane & 7;
    const uint32_t aOff = (uint32_t)(((wm * 64 + (q & 1) * 8 + i8) * SB + (q >> 1) * 8) * 2);
    const uint32_t bOff = (uint32_t)(((wn * 32 + (q >> 1) * 8 + i8) * SB + (q & 1) * 8) * 2);

    float acc[4][4][4];
#pragma unroll
    for (int mt = 0; mt < 4; ++mt)
#pragma unroll
        for (int nt = 0; nt < 4; ++nt)
#pragma unroll
            for (int e = 0; e < 4; ++e) acc[mt][nt][e] = 0.f;

    // stage k-chunk kt (32 k) into ring buffer 'buf'.
    // 1536 x 16B chunks = 3 tiles x 128 rows x 4 chunks; 6 per thread.
    auto stage = [&](int buf, int kt) {
        uint32_t base = smBase + buf * STAGEB;
        int kc = kt * 32;
#pragma unroll
        for (int i = 0; i < 6; ++i) {
            int c = tid + i * 256;              // 0..1535
            int hf = c & 3;                     // 16B chunk within row
            int r = (c >> 2) & 127;             // row within tile
            int tile = c >> 9;                  // 0=zh, 1=zl, 2=eh
            const __nv_bfloat16* src = (tile == 0) ? g_zh : (tile == 1) ? g_zl : g_cbh;
            int gr = (tile == 2) ? (codeBase + r) : (rowBase + r);
            cp16(base + (uint32_t)(tile * TILEB + r * (SB * 2) + hf * 16),
                 src + (size_t)gr * D + kc + hf * 8);
        }
        asm volatile("cp.async.commit_group;" ::: "memory");
    };

    stage(0, 0);
    stage(1, 1);
#pragma unroll
    for (int kt = 0; kt < 8; ++kt) {
        int buf = kt - (kt >= 3 ? 3 : 0) - (kt >= 6 ? 3 : 0);   // kt % 3
        if (kt < 7) asm volatile("cp.async.wait_group 1;" ::: "memory");
        else        asm volatile("cp.async.wait_group 0;" ::: "memory");
        __syncthreads();
        if (kt < 6) {
            int nb = kt + 2;
            stage(nb - (nb >= 3 ? 3 : 0) - (nb >= 6 ? 3 : 0), nb);
        }

        uint32_t tb = smBase + buf * STAGEB;
#pragma unroll
        for (int kh = 0; kh < 2; ++kh) {
            uint32_t ah[4][4], al[4][4], bfr[4][2];
#pragma unroll
            for (int mt = 0; mt < 4; ++mt)
                ldsm_x4(ah[mt][0], ah[mt][1], ah[mt][2], ah[mt][3],
                        tb + aOff + (uint32_t)(mt * 16 * SB * 2 + kh * 32));
#pragma unroll
            for (int mt = 0; mt < 4; ++mt)
                ldsm_x4(al[mt][0], al[mt][1], al[mt][2], al[mt][3],
                        tb + TILEB + aOff + (uint32_t)(mt * 16 * SB * 2 + kh * 32));
#pragma unroll
            for (int nt2 = 0; nt2 < 2; ++nt2) {
                uint32_t r0, r1, r2, r3;
                ldsm_x4(r0, r1, r2, r3,
                        tb + 2 * TILEB + bOff + (uint32_t)(nt2 * 16 * SB * 2 + kh * 32));
                bfr[nt2 * 2 + 0][0] = r0; bfr[nt2 * 2 + 0][1] = r1;
                bfr[nt2 * 2 + 1][0] = r2; bfr[nt2 * 2 + 1][1] = r3;
            }
#pragma unroll
            for (int mt = 0; mt < 4; ++mt)
#pragma unroll
                for (int nt = 0; nt < 4; ++nt) {
                    mma16816(acc[mt][nt], ah[mt][0], ah[mt][1], ah[mt][2], ah[mt][3],
                             bfr[nt][0], bfr[nt][1]);
                    mma16816(acc[mt][nt], al[mt][0], al[mt][1], al[mt][2], al[mt][3],
                             bfr[nt][0], bfr[nt][1]);
                }
        }
    }

    // ---- epilogue: d = cn - 2*dot, per-row top-2 over this CTA's 128 codes ----
    __syncthreads();                      // mainloop smem dead; alias as red[]
    float4 (*red)[4] = reinterpret_cast<float4(*)[4]>(smem);

    const int g = lane >> 2;
    const int cb0 = codeBase + wn * 32 + (lane & 3) * 2;
    float cn8[4][2];
#pragma unroll
    for (int nt = 0; nt < 4; ++nt) {
        cn8[nt][0] = __ldg(&g_cn[cb0 + nt * 8 + 0]);
        cn8[nt][1] = __ldg(&g_cn[cb0 + nt * 8 + 1]);
    }
#pragma unroll
    for (int mt = 0; mt < 4; ++mt)
#pragma unroll
        for (int h = 0; h < 2; ++h) {
            float v0 = CUDART_INF_F, v1 = CUDART_INF_F;
            int i0 = 0, i1 = 0;
#pragma unroll
            for (int nt = 0; nt < 4; ++nt)
#pragma unroll
                for (int e = 0; e < 2; ++e) {
                    float dd = fmaf(-2.f, acc[mt][nt][h * 2 + e], cn8[nt][e]);
                    int code = cb0 + nt * 8 + e;
                    if (dd < v0) { v1 = v0; i1 = i0; v0 = dd; i0 = code; }
                    else if (dd < v1) { v1 = dd; i1 = code; }
                }
#pragma unroll
            for (int off = 1; off <= 2; off <<= 1) {
                float w0 = __shfl_xor_sync(0xffffffffu, v0, off);
                float w1 = __shfl_xor_sync(0xffffffffu, v1, off);
                int j0 = __shfl_xor_sync(0xffffffffu, i0, off);
                int j1 = __shfl_xor_sync(0xffffffffu, i1, off);
                top2_merge(v0, i0, v1, i1, w0, j0, w1, j1);
            }
            if ((lane & 3) == 0)
                red[wm * 64 + mt * 16 + h * 8 + g][wn] =
                    make_float4(v0, __int_as_float(i0), v1, __int_as_float(i1));
        }
    __syncthreads();

    if (tid < 128) {
        float v0 = CUDART_INF_F, v1 = CUDART_INF_F;
        int i0 = 0, i1 = 0;
#pragma unroll
        for (int w = 0; w < 4; ++w) {
            float4 p = red[tid][w];
            top2_merge(v0, i0, v1, i1, p.x, __float_as_int(p.y), p.z, __float_as_int(p.w));
        }
        size_t slot = (size_t)(rowBase + tid) * gridDim.y + blockIdx.y;
        g_cv[slot] = make_float2(v0, v1);
        g_ci[slot] = make_int2(i0, i1);
    }
}

// ============================================================================
// Kernel 4: per-row reduce (approx top-4 of 2*NT candidates) + exact fp32
// rescore with d = cn - 2*z.e. One warp per row. NT <= 64.
// ============================================================================
__global__ __launch_bounds__(256)
void reduce_rescore_kernel(const float* __restrict__ z,
                           const float* __restrict__ cb, int NT) {
    int row = blockIdx.x * 8 + (threadIdx.x >> 5);
    int lane = threadIdx.x & 31;

    float v[4];
    int ix[4];
#pragma unroll
    for (int k = 0; k < 4; ++k) { v[k] = CUDART_INF_F; ix[k] = -1; }
#pragma unroll
    for (int p = 0; p < 2; ++p) {
        int s = lane + p * 32;
        if (s < NT) {
            float2 cv = g_cv[(size_t)row * NT + s];
            int2 ci = g_ci[(size_t)row * NT + s];
            v[p * 2 + 0] = cv.x; ix[p * 2 + 0] = ci.x;
            v[p * 2 + 1] = cv.y; ix[p * 2 + 1] = ci.y;
        }
    }

    float a0 = CUDART_INF_F, a1 = CUDART_INF_F; int b0 = -1, b1 = -1;
#pragma unroll
    for (int k = 0; k < 4; ++k) {
        if (v[k] < a0) { a1 = a0; b1 = b0; a0 = v[k]; b0 = ix[k]; }
        else if (v[k] < a1) { a1 = v[k]; b1 = ix[k]; }
    }
#pragma unroll
    for (int off = 16; off > 0; off >>= 1) {
        float w0 = __shfl_xor_sync(0xffffffffu, a0, off);
        float w1 = __shfl_xor_sync(0xffffffffu, a1, off);
        int j0 = __shfl_xor_sync(0xffffffffu, b0, off);
        int j1 = __shfl_xor_sync(0xffffffffu, b1, off);
        top2_merge(a0, b0, a1, b1, w0, j0, w1, j1);
    }
    int t0 = b0, t1 = b1;

    float c0 = CUDART_INF_F, c1 = CUDART_INF_F; int d0 = -1, d1 = -1;
#pragma unroll
    for (int k = 0; k < 4; ++k) {
        if (ix[k] != t0 && ix[k] != t1 && ix[k] >= 0) {
            if (v[k] < c0) { c1 = c0; d1 = d0; c0 = v[k]; d0 = ix[k]; }
            else if (v[k] < c1) { c1 = v[k]; d1 = ix[k]; }
        }
    }
#pragma unroll
    for (int off = 16; off > 0; off >>= 1) {
        float w0 = __shfl_xor_sync(0xffffffffu, c0, off);
        float w1 = __shfl_xor_sync(0xffffffffu, c1, off);
        int j0 = __shfl_xor_sync(0xffffffffu, d0, off);
        int j1 = __shfl_xor_sync(0xffffffffu, d1, off);
        top2_merge(c0, d0, c1, d1, w0, j0, w1, j1);
    }

    int jj[4] = { t0, t1, (d0 >= 0 ? d0 : t0), (d1 >= 0 ? d1 : t1) };

    const float4* zr = reinterpret_cast<const float4*>(z + (size_t)row * D);
    const float4* e0 = reinterpret_cast<const float4*>(cb + (size_t)jj[0] * D);
    const float4* e1 = reinterpret_cast<const float4*>(cb + (size_t)jj[1] * D);
    const float4* e2 = reinterpret_cast<const float4*>(cb + (size_t)jj[2] * D);
    const float4* e3 = reinterpret_cast<const float4*>(cb + (size_t)jj[3] * D);
    float s0 = 0.f, s1 = 0.f, s2 = 0.f, s3 = 0.f;
#pragma unroll
    for (int p = 0; p < 2; ++p) {
        int qd = lane + p * 32;
        float4 zv = zr[qd];
        float4 a = e0[qd];
        s0 = fmaf(zv.x, a.x, s0); s0 = fmaf(zv.y, a.y, s0);
        s0 = fmaf(zv.z, a.z, s0); s0 = fmaf(zv.w, a.w, s0);
        a = e1[qd];
        s1 = fmaf(zv.x, a.x, s1); s1 = fmaf(zv.y, a.y, s1);
        s1 = fmaf(zv.z, a.z, s1); s1 = fmaf(zv.w, a.w, s1);
        a = e2[qd];
        s2 = fmaf(zv.x, a.x, s2); s2 = fmaf(zv.y, a.y, s2);
        s2 = fmaf(zv.z, a.z, s2); s2 = fmaf(zv.w, a.w, s2);
        a = e3[qd];
        s3 = fmaf(zv.x, a.x, s3); s3 = fmaf(zv.y, a.y, s3);
        s3 = fmaf(zv.z, a.z, s3); s3 = fmaf(zv.w, a.w, s3);
    }
#pragma unroll
    for (int off = 16; off > 0; off >>= 1) {
        s0 += __shfl_xor_sync(0xffffffffu, s0, off);
        s1 += __shfl_xor_sync(0xffffffffu, s1, off);
        s2 += __shfl_xor_sync(0xffffffffu, s2, off);
        s3 += __shfl_xor_sync(0xffffffffu, s3, off);
    }
    if (lane == 0) {
        float dj[4];
        dj[0] = g_cn[jj[0]] - 2.f * s0;
        dj[1] = g_cn[jj[1]] - 2.f * s1;
        dj[2] = g_cn[jj[2]] - 2.f * s2;
        dj[3] = g_cn[jj[3]] - 2.f * s3;
        float best = dj[0]; int bi = jj[0];
#pragma unroll
        for (int k = 1; k < 4; ++k)
            if (dj[k] < best || (dj[k] == best && jj[k] < bi)) { best = dj[k]; bi = jj[k]; }
        g_idx[row] = bi;
    }
}

// ============================================================================
// Kernel 5: gather + straight-through recon + loss partials
// ============================================================================
__global__ void gather_loss_kernel(float* __restrict__ out,
                                   const float* __restrict__ cb,
                                   int total4) {
    int t = blockIdx.x * blockDim.x + threadIdx.x;
    int stride = gridDim.x * blockDim.x;
    float s = 0.f;
    for (int e4 = t; e4 < total4; e4 += stride) {
        int n = e4 >> 6;
        int c4 = e4 & 63;
        int k = g_idx[n];
        float4 qv = reinterpret_cast<const float4*>(cb + (size_t)k * D)[c4];
        float4 zv = reinterpret_cast<float4*>(out)[e4];
        reinterpret_cast<float4*>(out)[e4] = qv;   // z + (q - z) == q
        float dx = zv.x - qv.x, dy = zv.y - qv.y, dz = zv.z - qv.z, dw = zv.w - qv.w;
        s += dx * dx + dy * dy + dz * dz + dw * dw;
    }
    __shared__ float sr[256];
    sr[threadIdx.x] = s;
    __syncthreads();
    for (int st = 128; st > 0; st >>= 1) {
        if (threadIdx.x < st) sr[threadIdx.x] += sr[threadIdx.x + st];
        __syncthreads();
    }
    if (threadIdx.x == 0) g_part[blockIdx.x] = sr[0];
}

// ============================================================================
// Kernel 6: finalize losses
// ============================================================================
__global__ void finalize_kernel(float* __restrict__ out, int out_size,
                                float inv_count) {
    __shared__ float sr[512];
    int t = threadIdx.x;
    sr[t] = g_part[t];
    __syncthreads();
    for (int st = 256; st > 0; st >>= 1) {
        if (t < st) sr[t] += sr[t + st];
        __syncthreads();
    }
    if (t == 0) {
        float m = sr[0] * inv_count;
        out[out_size - 2] = m;
        out[out_size - 1] = m;
    }
}

// ============================================================================
extern "C" void kernel_launch(void* const* d_in, const int* in_sizes, int n_in,
                              void* d_out, int out_size) {
    const float* x  = (const float*)d_in[0];
    const float* W  = (const float*)d_in[1];
    const float* b  = (const float*)d_in[2];
    const float* cb = (const float*)d_in[3];

    int M      = in_sizes[0] / D;   // 32768
    int Kcodes = in_sizes[3] / D;   // 8192
    int NT     = Kcodes / 128;      // 64
    float* out = (float*)d_out;

    cudaFuncSetAttribute(dist_mma_kernel,
                         cudaFuncAttributeMaxDynamicSharedMemorySize, DIST_SMEM);

    // 1. fused codebook norms + bf16 hi split
    cnsplit_kernel<<<Kcodes / 8, 256>>>(cb);

    // 2. projection (exact fp32 z into out, plus bf16 hi/lo of z)
    dim3 pg(M / BM, D / BN);
    proj_kernel<<<pg, NTHREADS>>>(x, W, b, out);

    // 3. HMMA distance GEMM (2-term, 128x128 tiles, BK=32, 3-stage, 2 CTA/SM)
    dist_mma_kernel<<<dim3(M / 128, NT), 256, DIST_SMEM>>>(Kcodes);

    // 4. reduce candidates + exact fp32 rescore of top-4
    reduce_rescore_kernel<<<M / 8, 256>>>(out, cb, NT);

    // 5. gather + losses
    gather_loss_kernel<<<512, 256>>>(out, cb, (M * D) / 4);

    // 6. finalize
    finalize_kernel<<<1, 512>>>(out, out_size, 1.0f / (float)(M * D));
}

// round 7
// speedup vs baseline: 1.4837x; 1.1154x over previous
#include <cuda_runtime.h>
#include <cuda_bf16.h>
#include <math_constants.h>
#include <cstdint>

// ============================================================================
// Problem constants
// ============================================================================
#define D        256
#define MROWS    32768
#define KCODES   8192
#define NTILE    64            // KCODES / 128
#define BM       128
#define BN       128
#define BK       16
#define TM       8
#define TN       8
#define NTHREADS 256

// dist kernel smem geometry (BK = 32)
#define SB       40                    // smem row stride in bf16 (80 B, conflict-free)
#define TILEB    (128 * SB * 2)        // 10240 B per 128x32 tile
#define STAGEB   (3 * TILEB)           // zh + zl + eh = 30720 B per stage
#define NSTAGE   3
#define DIST_SMEM (NSTAGE * STAGEB)    // 92160 B -> 2 CTAs/SM

// ============================================================================
// Device scratch (no cudaMalloc allowed)
// ============================================================================
__device__ float          g_cn[KCODES];
__device__ float          g_part[4096];
__device__ __nv_bfloat16  g_cbh[KCODES * D];
__device__ __nv_bfloat16  g_zh[MROWS * D];
__device__ __nv_bfloat16  g_zl[MROWS * D];
__device__ float2         g_cv[(size_t)MROWS * NTILE];
__device__ int2           g_ci[(size_t)MROWS * NTILE];

// ============================================================================
// Helpers
// ============================================================================
__device__ __forceinline__ uint32_t smem_to_u32(const void* p) {
    uint32_t a;
    asm("{ .reg .u64 t; cvta.to.shared.u64 t, %1; cvt.u32.u64 %0, t; }"
        : "=r"(a) : "l"(p));
    return a;
}
__device__ __forceinline__ void cp16(uint32_t dst, const void* src) {
    asm volatile("cp.async.cg.shared.global [%0], [%1], 16;"
        :: "r"(dst), "l"(__cvta_generic_to_global(src)) : "memory");
}
__device__ __forceinline__ void ldsm_x4(uint32_t& r0, uint32_t& r1,
                                        uint32_t& r2, uint32_t& r3, uint32_t addr) {
    asm volatile("ldmatrix.sync.aligned.m8n8.x4.shared.b16 {%0,%1,%2,%3}, [%4];"
        : "=r"(r0), "=r"(r1), "=r"(r2), "=r"(r3) : "r"(addr));
}
__device__ __forceinline__ void mma16816(float* c, uint32_t a0, uint32_t a1,
                                         uint32_t a2, uint32_t a3,
                                         uint32_t b0, uint32_t b1) {
    asm volatile("mma.sync.aligned.m16n8k16.row.col.f32.bf16.bf16.f32 "
        "{%0,%1,%2,%3}, {%4,%5,%6,%7}, {%8,%9}, {%0,%1,%2,%3};"
        : "+f"(c[0]), "+f"(c[1]), "+f"(c[2]), "+f"(c[3])
        : "r"(a0), "r"(a1), "r"(a2), "r"(a3), "r"(b0), "r"(b1));
}
__device__ __forceinline__ void top2_merge(float& v0, int& i0, float& v1, int& i1,
                                           float w0, int j0, float w1, int j1) {
    if (w0 < v0) {
        if (v0 < w1) { v1 = v0; i1 = i0; } else { v1 = w1; i1 = j1; }
        v0 = w0; i0 = j0;
    } else if (w0 < v1) { v1 = w0; i1 = j0; }
}

// ============================================================================
// Kernel 1: fused codebook norms + bf16 hi-split (one pass over cb)
// ============================================================================
__global__ __launch_bounds__(256)
void cnsplit_kernel(const float* __restrict__ cb) {
    int row = blockIdx.x * 8 + (threadIdx.x >> 5);
    int lane = threadIdx.x & 31;
    const float4* src = reinterpret_cast<const float4*>(cb + (size_t)row * D);
    __nv_bfloat162* dh = reinterpret_cast<__nv_bfloat162*>(g_cbh + (size_t)row * D);
    float s = 0.f;
#pragma unroll
    for (int p = 0; p < 2; ++p) {
        int q = lane + p * 32;
        float4 v = src[q];
        s += v.x * v.x + v.y * v.y + v.z * v.z + v.w * v.w;
        dh[q * 2 + 0] = __nv_bfloat162(__float2bfloat16(v.x), __float2bfloat16(v.y));
        dh[q * 2 + 1] = __nv_bfloat162(__float2bfloat16(v.z), __float2bfloat16(v.w));
    }
#pragma unroll
    for (int o = 16; o > 0; o >>= 1) s += __shfl_xor_sync(0xffffffffu, s, o);
    if (lane == 0) g_cn[row] = s;
}

// ============================================================================
// Kernel 2: projection z = x W^T + b (exact fp32 SIMT) + bf16 hi/lo split of z
// ============================================================================
__device__ __forceinline__ void load_tile(float dst[BK][BM + 4],
                                          const float* __restrict__ src,
                                          int rowBase, int kt, int tid) {
#pragma unroll
    for (int p = 0; p < 2; ++p) {
        int id = tid + p * NTHREADS;
        int r = id >> 2, c4 = id & 3;
        float4 v = *reinterpret_cast<const float4*>(
            src + (size_t)(rowBase + r) * D + kt * BK + c4 * 4);
        dst[c4 * 4 + 0][r] = v.x;
        dst[c4 * 4 + 1][r] = v.y;
        dst[c4 * 4 + 2][r] = v.z;
        dst[c4 * 4 + 3][r] = v.w;
    }
}

__global__ __launch_bounds__(NTHREADS, 2)
void proj_kernel(const float* __restrict__ x, const float* __restrict__ W,
                 const float* __restrict__ b, float* __restrict__ z) {
    __shared__ float Xs[BK][BM + 4];
    __shared__ float Ws[BK][BN + 4];

    int tid = threadIdx.x;
    int tx = tid & 15, ty = tid >> 4;
    int rowBase = blockIdx.x * BM;
    int colBase = blockIdx.y * BN;

    float acc[TM][TN];
#pragma unroll
    for (int i = 0; i < TM; ++i)
#pragma unroll
        for (int j = 0; j < TN; ++j) acc[i][j] = 0.f;

    for (int kt = 0; kt < D / BK; ++kt) {
        load_tile(Xs, x, rowBase, kt, tid);
        load_tile(Ws, W, colBase, kt, tid);
        __syncthreads();
#pragma unroll
        for (int kk = 0; kk < BK; ++kk) {
            float a[TM], bb[TN];
#pragma unroll
            for (int i = 0; i < TM; ++i) a[i] = Xs[kk][ty * TM + i];
#pragma unroll
            for (int j = 0; j < TN; ++j) bb[j] = Ws[kk][tx * TN + j];
#pragma unroll
            for (int i = 0; i < TM; ++i)
#pragma unroll
                for (int j = 0; j < TN; ++j)
                    acc[i][j] = fmaf(a[i], bb[j], acc[i][j]);
        }
        __syncthreads();
    }

    int col0 = colBase + tx * TN;
#pragma unroll
    for (int i = 0; i < TM; ++i) {
        int row = rowBase + ty * TM + i;
        float* zrow = z + (size_t)row * D + col0;
        __nv_bfloat162* hrow = reinterpret_cast<__nv_bfloat162*>(g_zh + (size_t)row * D) + (col0 >> 1);
        __nv_bfloat162* lrow = reinterpret_cast<__nv_bfloat162*>(g_zl + (size_t)row * D) + (col0 >> 1);
#pragma unroll
        for (int j4 = 0; j4 < TN / 4; ++j4) {
            float4 v;
            v.x = acc[i][j4 * 4 + 0] + b[col0 + j4 * 4 + 0];
            v.y = acc[i][j4 * 4 + 1] + b[col0 + j4 * 4 + 1];
            v.z = acc[i][j4 * 4 + 2] + b[col0 + j4 * 4 + 2];
            v.w = acc[i][j4 * 4 + 3] + b[col0 + j4 * 4 + 3];
            *reinterpret_cast<float4*>(zrow + j4 * 4) = v;
            __nv_bfloat16 h0 = __float2bfloat16(v.x), h1 = __float2bfloat16(v.y);
            __nv_bfloat16 h2 = __float2bfloat16(v.z), h3 = __float2bfloat16(v.w);
            hrow[j4 * 2 + 0] = __nv_bfloat162(h0, h1);
            hrow[j4 * 2 + 1] = __nv_bfloat162(h2, h3);
            lrow[j4 * 2 + 0] = __nv_bfloat162(__float2bfloat16(v.x - __bfloat162float(h0)),
                                              __float2bfloat16(v.y - __bfloat162float(h1)));
            lrow[j4 * 2 + 1] = __nv_bfloat162(__float2bfloat16(v.z - __bfloat162float(h2)),
                                              __float2bfloat16(v.w - __bfloat162float(h3)));
        }
    }
}

// ============================================================================
// Kernel 3: distance GEMM on HMMA, 2-term split (dot = zh.eh + zl.eh = z.eh).
// CTA 128x128, 8 warps as 4(m) x 2(n), warp tile 32x64 -> 8 ldsm per 32 MMA.
// BK=32, 3-stage cp.async ring, 8 iterations, 1 barrier each, 2 CTAs/SM.
// ============================================================================
__global__ __launch_bounds__(256, 2)
void dist_mma_kernel(int Kcodes) {
    extern __shared__ __align__(16) char smem[];
    const uint32_t smBase = smem_to_u32(smem);

    const int tid = threadIdx.x, lane = tid & 31, wid = tid >> 5;
    const int wm = wid >> 1, wn = wid & 1;        // 4 x 2 warp grid
    const int rowBase = blockIdx.x * 128;
    const int codeBase = blockIdx.y * 128;

    // ldmatrix lane addressing (within a tile)
    const int q = lane >> 3, i8 = lane & 7;
    const uint32_t aOff = (uint32_t)(((wm * 32 + (q & 1) * 8 + i8) * SB + (q >> 1) * 8) * 2);
    const uint32_t bOff = (uint32_t)(((wn * 64 + (q >> 1) * 8 + i8) * SB + (q & 1) * 8) * 2);

    float acc[2][8][4];
#pragma unroll
    for (int mt = 0; mt < 2; ++mt)
#pragma unroll
        for (int nt = 0; nt < 8; ++nt)
#pragma unroll
            for (int e = 0; e < 4; ++e) acc[mt][nt][e] = 0.f;

    // stage k-chunk kt (32 k) into ring buffer 'buf'.
    auto stage = [&](int buf, int kt) {
        uint32_t base = smBase + buf * STAGEB;
        int kc = kt * 32;
#pragma unroll
        for (int i = 0; i < 6; ++i) {
            int c = tid + i * 256;              // 0..1535
            int hf = c & 3;
            int r = (c >> 2) & 127;
            int tile = c >> 9;                  // 0=zh, 1=zl, 2=eh
            const __nv_bfloat16* src = (tile == 0) ? g_zh : (tile == 1) ? g_zl : g_cbh;
            int gr = (tile == 2) ? (codeBase + r) : (rowBase + r);
            cp16(base + (uint32_t)(tile * TILEB + r * (SB * 2) + hf * 16),
                 src + (size_t)gr * D + kc + hf * 8);
        }
        asm volatile("cp.async.commit_group;" ::: "memory");
    };

    stage(0, 0);
    stage(1, 1);
#pragma unroll
    for (int kt = 0; kt < 8; ++kt) {
        int buf = kt - (kt >= 3 ? 3 : 0) - (kt >= 6 ? 3 : 0);   // kt % 3
        if (kt < 7) asm volatile("cp.async.wait_group 1;" ::: "memory");
        else        asm volatile("cp.async.wait_group 0;" ::: "memory");
        __syncthreads();
        if (kt < 6) {
            int nb = kt + 2;
            stage(nb - (nb >= 3 ? 3 : 0) - (nb >= 6 ? 3 : 0), nb);
        }

        uint32_t tb = smBase + buf * STAGEB;
#pragma unroll
        for (int kh = 0; kh < 2; ++kh) {
            uint32_t ah[2][4], al[2][4], bfr[8][2];
#pragma unroll
            for (int mt = 0; mt < 2; ++mt)
                ldsm_x4(ah[mt][0], ah[mt][1], ah[mt][2], ah[mt][3],
                        tb + aOff + (uint32_t)(mt * 16 * SB * 2 + kh * 32));
#pragma unroll
            for (int mt = 0; mt < 2; ++mt)
                ldsm_x4(al[mt][0], al[mt][1], al[mt][2], al[mt][3],
                        tb + TILEB + aOff + (uint32_t)(mt * 16 * SB * 2 + kh * 32));
#pragma unroll
            for (int nt2 = 0; nt2 < 4; ++nt2) {
                uint32_t r0, r1, r2, r3;
                ldsm_x4(r0, r1, r2, r3,
                        tb + 2 * TILEB + bOff + (uint32_t)(nt2 * 16 * SB * 2 + kh * 32));
                bfr[nt2 * 2 + 0][0] = r0; bfr[nt2 * 2 + 0][1] = r1;
                bfr[nt2 * 2 + 1][0] = r2; bfr[nt2 * 2 + 1][1] = r3;
            }
#pragma unroll
            for (int mt = 0; mt < 2; ++mt)
#pragma unroll
                for (int nt = 0; nt < 8; ++nt) {
                    mma16816(acc[mt][nt], ah[mt][0], ah[mt][1], ah[mt][2], ah[mt][3],
                             bfr[nt][0], bfr[nt][1]);
                    mma16816(acc[mt][nt], al[mt][0], al[mt][1], al[mt][2], al[mt][3],
                             bfr[nt][0], bfr[nt][1]);
                }
        }
    }

    // ---- epilogue: d = cn - 2*dot, per-row top-2 over this CTA's 128 codes ----
    __syncthreads();                      // mainloop smem dead; alias as red[]
    float4 (*red)[2] = reinterpret_cast<float4(*)[2]>(smem);

    const int g = lane >> 2;
    const int cb0 = codeBase + wn * 64 + (lane & 3) * 2;
    float cn8[8][2];
#pragma unroll
    for (int nt = 0; nt < 8; ++nt) {
        cn8[nt][0] = __ldg(&g_cn[cb0 + nt * 8 + 0]);
        cn8[nt][1] = __ldg(&g_cn[cb0 + nt * 8 + 1]);
    }
#pragma unroll
    for (int mt = 0; mt < 2; ++mt)
#pragma unroll
        for (int h = 0; h < 2; ++h) {
            float v0 = CUDART_INF_F, v1 = CUDART_INF_F;
            int i0 = 0, i1 = 0;
#pragma unroll
            for (int nt = 0; nt < 8; ++nt)
#pragma unroll
                for (int e = 0; e < 2; ++e) {
                    float dd = fmaf(-2.f, acc[mt][nt][h * 2 + e], cn8[nt][e]);
                    int code = cb0 + nt * 8 + e;
                    if (dd < v0) { v1 = v0; i1 = i0; v0 = dd; i0 = code; }
                    else if (dd < v1) { v1 = dd; i1 = code; }
                }
#pragma unroll
            for (int off = 1; off <= 2; off <<= 1) {
                float w0 = __shfl_xor_sync(0xffffffffu, v0, off);
                float w1 = __shfl_xor_sync(0xffffffffu, v1, off);
                int j0 = __shfl_xor_sync(0xffffffffu, i0, off);
                int j1 = __shfl_xor_sync(0xffffffffu, i1, off);
                top2_merge(v0, i0, v1, i1, w0, j0, w1, j1);
            }
            if ((lane & 3) == 0)
                red[wm * 32 + mt * 16 + h * 8 + g][wn] =
                    make_float4(v0, __int_as_float(i0), v1, __int_as_float(i1));
        }
    __syncthreads();

    if (tid < 128) {
        float4 p0 = red[tid][0];
        float4 p1 = red[tid][1];
        float v0 = p0.x, v1 = p0.z;
        int i0 = __float_as_int(p0.y), i1 = __float_as_int(p0.w);
        top2_merge(v0, i0, v1, i1, p1.x, __float_as_int(p1.y), p1.z, __float_as_int(p1.w));
        size_t slot = (size_t)(rowBase + tid) * gridDim.y + blockIdx.y;
        g_cv[slot] = make_float2(v0, v1);
        g_ci[slot] = make_int2(i0, i1);
    }
}

// ============================================================================
// Kernel 4 (fused): per-row top-4 reduce + exact fp32 rescore + gather q into
// out + elementwise loss partial. One warp per row; 8 rows per block.
// ============================================================================
__global__ __launch_bounds__(256)
void rescore_gather_kernel(float* __restrict__ out,
                           const float* __restrict__ cb, int NT) {
    __shared__ float wloss[8];
    int warp = threadIdx.x >> 5;
    int row = blockIdx.x * 8 + warp;
    int lane = threadIdx.x & 31;

    float v[4];
    int ix[4];
#pragma unroll
    for (int k = 0; k < 4; ++k) { v[k] = CUDART_INF_F; ix[k] = -1; }
#pragma unroll
    for (int p = 0; p < 2; ++p) {
        int s = lane + p * 32;
        if (s < NT) {
            float2 cv = g_cv[(size_t)row * NT + s];
            int2 ci = g_ci[(size_t)row * NT + s];
            v[p * 2 + 0] = cv.x; ix[p * 2 + 0] = ci.x;
            v[p * 2 + 1] = cv.y; ix[p * 2 + 1] = ci.y;
        }
    }

    // approx top-2
    float a0 = CUDART_INF_F, a1 = CUDART_INF_F; int b0 = -1, b1 = -1;
#pragma unroll
    for (int k = 0; k < 4; ++k) {
        if (v[k] < a0) { a1 = a0; b1 = b0; a0 = v[k]; b0 = ix[k]; }
        else if (v[k] < a1) { a1 = v[k]; b1 = ix[k]; }
    }
#pragma unroll
    for (int off = 16; off > 0; off >>= 1) {
        float w0 = __shfl_xor_sync(0xffffffffu, a0, off);
        float w1 = __shfl_xor_sync(0xffffffffu, a1, off);
        int j0 = __shfl_xor_sync(0xffffffffu, b0, off);
        int j1 = __shfl_xor_sync(0xffffffffu, b1, off);
        top2_merge(a0, b0, a1, b1, w0, j0, w1, j1);
    }
    int t0 = b0, t1 = b1;

    // approx ranks 3-4
    float c0 = CUDART_INF_F, c1 = CUDART_INF_F; int d0 = -1, d1 = -1;
#pragma unroll
    for (int k = 0; k < 4; ++k) {
        if (ix[k] != t0 && ix[k] != t1 && ix[k] >= 0) {
            if (v[k] < c0) { c1 = c0; d1 = d0; c0 = v[k]; d0 = ix[k]; }
            else if (v[k] < c1) { c1 = v[k]; d1 = ix[k]; }
        }
    }
#pragma unroll
    for (int off = 16; off > 0; off >>= 1) {
        float w0 = __shfl_xor_sync(0xffffffffu, c0, off);
        float w1 = __shfl_xor_sync(0xffffffffu, c1, off);
        int j0 = __shfl_xor_sync(0xffffffffu, d0, off);
        int j1 = __shfl_xor_sync(0xffffffffu, d1, off);
        top2_merge(c0, d0, c1, d1, w0, j0, w1, j1);
    }

    int jj[4] = { t0, t1, (d0 >= 0 ? d0 : t0), (d1 >= 0 ? d1 : t1) };

    // exact fp32 rescore: d_j = cn[j] - 2 * z.e_j
    float4* zr = reinterpret_cast<float4*>(out + (size_t)row * D);
    const float4* e0 = reinterpret_cast<const float4*>(cb + (size_t)jj[0] * D);
    const float4* e1 = reinterpret_cast<const float4*>(cb + (size_t)jj[1] * D);
    const float4* e2 = reinterpret_cast<const float4*>(cb + (size_t)jj[2] * D);
    const float4* e3 = reinterpret_cast<const float4*>(cb + (size_t)jj[3] * D);
    float s0 = 0.f, s1 = 0.f, s2 = 0.f, s3 = 0.f;
#pragma unroll
    for (int p = 0; p < 2; ++p) {
        int qd = lane + p * 32;
        float4 zv = zr[qd];
        float4 a = e0[qd];
        s0 = fmaf(zv.x, a.x, s0); s0 = fmaf(zv.y, a.y, s0);
        s0 = fmaf(zv.z, a.z, s0); s0 = fmaf(zv.w, a.w, s0);
        a = e1[qd];
        s1 = fmaf(zv.x, a.x, s1); s1 = fmaf(zv.y, a.y, s1);
        s1 = fmaf(zv.z, a.z, s1); s1 = fmaf(zv.w, a.w, s1);
        a = e2[qd];
        s2 = fmaf(zv.x, a.x, s2); s2 = fmaf(zv.y, a.y, s2);
        s2 = fmaf(zv.z, a.z, s2); s2 = fmaf(zv.w, a.w, s2);
        a = e3[qd];
        s3 = fmaf(zv.x, a.x, s3); s3 = fmaf(zv.y, a.y, s3);
        s3 = fmaf(zv.z, a.z, s3); s3 = fmaf(zv.w, a.w, s3);
    }
#pragma unroll
    for (int off = 16; off > 0; off >>= 1) {
        s0 += __shfl_xor_sync(0xffffffffu, s0, off);
        s1 += __shfl_xor_sync(0xffffffffu, s1, off);
        s2 += __shfl_xor_sync(0xffffffffu, s2, off);
        s3 += __shfl_xor_sync(0xffffffffu, s3, off);
    }
    // every lane has all sums (butterfly) -> identical winner everywhere
    float dj0 = g_cn[jj[0]] - 2.f * s0;
    float dj1 = g_cn[jj[1]] - 2.f * s1;
    float dj2 = g_cn[jj[2]] - 2.f * s2;
    float dj3 = g_cn[jj[3]] - 2.f * s3;
    float best = dj0; int bi = jj[0];
    if (dj1 < best || (dj1 == best && jj[1] < bi)) { best = dj1; bi = jj[1]; }
    if (dj2 < best || (dj2 == best && jj[2] < bi)) { best = dj2; bi = jj[2]; }
    if (dj3 < best || (dj3 == best && jj[3] < bi)) { best = dj3; bi = jj[3]; }

    // gather q, write x_recon row (= q), accumulate elementwise loss
    const float4* ew = reinterpret_cast<const float4*>(cb + (size_t)bi * D);
    float ls = 0.f;
#pragma unroll
    for (int p = 0; p < 2; ++p) {
        int qd = lane + p * 32;
        float4 zv = zr[qd];
        float4 qv = ew[qd];
        zr[qd] = qv;
        float dx = zv.x - qv.x, dy = zv.y - qv.y;
        float dz = zv.z - qv.z, dw = zv.w - qv.w;
        ls += dx * dx + dy * dy + dz * dz + dw * dw;
    }
#pragma unroll
    for (int off = 16; off > 0; off >>= 1)
        ls += __shfl_xor_sync(0xffffffffu, ls, off);
    if (lane == 0) wloss[warp] = ls;
    __syncthreads();
    if (threadIdx.x == 0) {
        float t = 0.f;
#pragma unroll
        for (int w = 0; w < 8; ++w) t += wloss[w];
        g_part[blockIdx.x] = t;
    }
}

// ============================================================================
// Kernel 5: finalize losses (4096 partials, deterministic tree)
// ============================================================================
__global__ __launch_bounds__(1024)
void finalize_kernel(float* __restrict__ out, int out_size, float inv_count) {
    __shared__ float sr[1024];
    int t = threadIdx.x;
    float s = 0.f;
#pragma unroll
    for (int p = 0; p < 4; ++p) s += g_part[t + p * 1024];
    sr[t] = s;
    __syncthreads();
    for (int st = 512; st > 0; st >>= 1) {
        if (t < st) sr[t] += sr[t + st];
        __syncthreads();
    }
    if (t == 0) {
        float m = sr[0] * inv_count;
        out[out_size - 2] = m;
        out[out_size - 1] = m;
    }
}

// ============================================================================
extern "C" void kernel_launch(void* const* d_in, const int* in_sizes, int n_in,
                              void* d_out, int out_size) {
    const float* x  = (const float*)d_in[0];
    const float* W  = (const float*)d_in[1];
    const float* b  = (const float*)d_in[2];
    const float* cb = (const float*)d_in[3];

    int M      = in_sizes[0] / D;   // 32768
    int Kcodes = in_sizes[3] / D;   // 8192
    int NT     = Kcodes / 128;      // 64
    float* out = (float*)d_out;

    cudaFuncSetAttribute(dist_mma_kernel,
                         cudaFuncAttributeMaxDynamicSharedMemorySize, DIST_SMEM);

    // 1. fused codebook norms + bf16 hi split
    cnsplit_kernel<<<Kcodes / 8, 256>>>(cb);

    // 2. projection (exact fp32 z into out, plus bf16 hi/lo of z)
    dim3 pg(M / BM, D / BN);
    proj_kernel<<<pg, NTHREADS>>>(x, W, b, out);

    // 3. HMMA distance GEMM (2-term, 128x128 tiles, warp 32x64, 2 CTA/SM)
    dist_mma_kernel<<<dim3(M / 128, NT), 256, DIST_SMEM>>>(Kcodes);

    // 4. fused reduce + exact rescore + gather + loss partials
    rescore_gather_kernel<<<M / 8, 256>>>(out, cb, NT);

    // 5. finalize
    finalize_kernel<<<1, 1024>>>(out, out_size, 1.0f / (float)(M * D));
}

// round 8
// speedup vs baseline: 1.8558x; 1.2508x over previous
#include <cuda_runtime.h>
#include <cuda_bf16.h>
#include <math_constants.h>
#include <cstdint>

// ============================================================================
// Problem constants
// ============================================================================
#define D        256
#define MROWS    32768
#define KCODES   8192
#define NTILE    64            // KCODES / 128
#define BM       128
#define BN       128
#define BK       16
#define TM       8
#define TN       8
#define NTHREADS 256

// dist kernel smem geometry (BK = 32, 2 tiles per stage: zh, eh)
#define SB       40                    // smem row stride in bf16 (80 B, conflict-free)
#define TILEB    (128 * SB * 2)        // 10240 B per 128x32 tile
#define STAGEB   (2 * TILEB)           // zh + eh = 20480 B per stage
#define NSTAGE   3
#define DIST_SMEM (NSTAGE * STAGEB)    // 61440 B -> 2 CTAs/SM

// ============================================================================
// Device scratch (no cudaMalloc allowed)
// ============================================================================
__device__ float          g_cn[KCODES];
__device__ float          g_part[4096];
__device__ __nv_bfloat16  g_cbh[KCODES * D];
__device__ __nv_bfloat16  g_zh[MROWS * D];
__device__ float2         g_cv[(size_t)MROWS * NTILE];
__device__ int2           g_ci[(size_t)MROWS * NTILE];

// ============================================================================
// Helpers
// ============================================================================
__device__ __forceinline__ uint32_t smem_to_u32(const void* p) {
    uint32_t a;
    asm("{ .reg .u64 t; cvta.to.shared.u64 t, %1; cvt.u32.u64 %0, t; }"
        : "=r"(a) : "l"(p));
    return a;
}
__device__ __forceinline__ void cp16(uint32_t dst, const void* src) {
    asm volatile("cp.async.cg.shared.global [%0], [%1], 16;"
        :: "r"(dst), "l"(__cvta_generic_to_global(src)) : "memory");
}
__device__ __forceinline__ void ldsm_x4(uint32_t& r0, uint32_t& r1,
                                        uint32_t& r2, uint32_t& r3, uint32_t addr) {
    asm volatile("ldmatrix.sync.aligned.m8n8.x4.shared.b16 {%0,%1,%2,%3}, [%4];"
        : "=r"(r0), "=r"(r1), "=r"(r2), "=r"(r3) : "r"(addr));
}
__device__ __forceinline__ void mma16816(float* c, uint32_t a0, uint32_t a1,
                                         uint32_t a2, uint32_t a3,
                                         uint32_t b0, uint32_t b1) {
    asm volatile("mma.sync.aligned.m16n8k16.row.col.f32.bf16.bf16.f32 "
        "{%0,%1,%2,%3}, {%4,%5,%6,%7}, {%8,%9}, {%0,%1,%2,%3};"
        : "+f"(c[0]), "+f"(c[1]), "+f"(c[2]), "+f"(c[3])
        : "r"(a0), "r"(a1), "r"(a2), "r"(a3), "r"(b0), "r"(b1));
}
__device__ __forceinline__ void top2_merge(float& v0, int& i0, float& v1, int& i1,
                                           float w0, int j0, float w1, int j1) {
    if (w0 < v0) {
        if (v0 < w1) { v1 = v0; i1 = i0; } else { v1 = w1; i1 = j1; }
        v0 = w0; i0 = j0;
    } else if (w0 < v1) { v1 = w0; i1 = j0; }
}

// ============================================================================
// Kernel 1: fused codebook norms + bf16 hi-split (one pass over cb)
// ============================================================================
__global__ __launch_bounds__(256)
void cnsplit_kernel(const float* __restrict__ cb) {
    int row = blockIdx.x * 8 + (threadIdx.x >> 5);
    int lane = threadIdx.x & 31;
    const float4* src = reinterpret_cast<const float4*>(cb + (size_t)row * D);
    __nv_bfloat162* dh = reinterpret_cast<__nv_bfloat162*>(g_cbh + (size_t)row * D);
    float s = 0.f;
#pragma unroll
    for (int p = 0; p < 2; ++p) {
        int q = lane + p * 32;
        float4 v = src[q];
        s += v.x * v.x + v.y * v.y + v.z * v.z + v.w * v.w;
        dh[q * 2 + 0] = __nv_bfloat162(__float2bfloat16(v.x), __float2bfloat16(v.y));
        dh[q * 2 + 1] = __nv_bfloat162(__float2bfloat16(v.z), __float2bfloat16(v.w));
    }
#pragma unroll
    for (int o = 16; o > 0; o >>= 1) s += __shfl_xor_sync(0xffffffffu, s, o);
    if (lane == 0) g_cn[row] = s;
}

// ============================================================================
// Kernel 2: projection z = x W^T + b (exact fp32 SIMT) + bf16 hi split of z
// ============================================================================
__device__ __forceinline__ void load_tile(float dst[BK][BM + 4],
                                          const float* __restrict__ src,
                                          int rowBase, int kt, int tid) {
#pragma unroll
    for (int p = 0; p < 2; ++p) {
        int id = tid + p * NTHREADS;
        int r = id >> 2, c4 = id & 3;
        float4 v = *reinterpret_cast<const float4*>(
            src + (size_t)(rowBase + r) * D + kt * BK + c4 * 4);
        dst[c4 * 4 + 0][r] = v.x;
        dst[c4 * 4 + 1][r] = v.y;
        dst[c4 * 4 + 2][r] = v.z;
        dst[c4 * 4 + 3][r] = v.w;
    }
}

__global__ __launch_bounds__(NTHREADS, 2)
void proj_kernel(const float* __restrict__ x, const float* __restrict__ W,
                 const float* __restrict__ b, float* __restrict__ z) {
    __shared__ float Xs[BK][BM + 4];
    __shared__ float Ws[BK][BN + 4];

    int tid = threadIdx.x;
    int tx = tid & 15, ty = tid >> 4;
    int rowBase = blockIdx.x * BM;
    int colBase = blockIdx.y * BN;

    float acc[TM][TN];
#pragma unroll
    for (int i = 0; i < TM; ++i)
#pragma unroll
        for (int j = 0; j < TN; ++j) acc[i][j] = 0.f;

    for (int kt = 0; kt < D / BK; ++kt) {
        load_tile(Xs, x, rowBase, kt, tid);
        load_tile(Ws, W, colBase, kt, tid);
        __syncthreads();
#pragma unroll
        for (int kk = 0; kk < BK; ++kk) {
            float a[TM], bb[TN];
#pragma unroll
            for (int i = 0; i < TM; ++i) a[i] = Xs[kk][ty * TM + i];
#pragma unroll
            for (int j = 0; j < TN; ++j) bb[j] = Ws[kk][tx * TN + j];
#pragma unroll
            for (int i = 0; i < TM; ++i)
#pragma unroll
                for (int j = 0; j < TN; ++j)
                    acc[i][j] = fmaf(a[i], bb[j], acc[i][j]);
        }
        __syncthreads();
    }

    int col0 = colBase + tx * TN;
#pragma unroll
    for (int i = 0; i < TM; ++i) {
        int row = rowBase + ty * TM + i;
        float* zrow = z + (size_t)row * D + col0;
        __nv_bfloat162* hrow = reinterpret_cast<__nv_bfloat162*>(g_zh + (size_t)row * D) + (col0 >> 1);
#pragma unroll
        for (int j4 = 0; j4 < TN / 4; ++j4) {
            float4 v;
            v.x = acc[i][j4 * 4 + 0] + b[col0 + j4 * 4 + 0];
            v.y = acc[i][j4 * 4 + 1] + b[col0 + j4 * 4 + 1];
            v.z = acc[i][j4 * 4 + 2] + b[col0 + j4 * 4 + 2];
            v.w = acc[i][j4 * 4 + 3] + b[col0 + j4 * 4 + 3];
            *reinterpret_cast<float4*>(zrow + j4 * 4) = v;
            hrow[j4 * 2 + 0] = __nv_bfloat162(__float2bfloat16(v.x), __float2bfloat16(v.y));
            hrow[j4 * 2 + 1] = __nv_bfloat162(__float2bfloat16(v.z), __float2bfloat16(v.w));
        }
    }
}

// ============================================================================
// Kernel 3: distance GEMM on HMMA, 1-term (dot = zh.eh; rounding noise is
// absorbed by exact top-8 rescore). CTA 128x128, warp grid 4(m) x 2(n),
// warp tile 32x64. BK=32, 3-stage cp.async ring, 2 CTAs/SM.
// ============================================================================
__global__ __launch_bounds__(256, 2)
void dist_mma_kernel(int Kcodes) {
    extern __shared__ __align__(16) char smem[];
    const uint32_t smBase = smem_to_u32(smem);

    const int tid = threadIdx.x, lane = tid & 31, wid = tid >> 5;
    const int wm = wid >> 1, wn = wid & 1;        // 4 x 2 warp grid
    const int rowBase = blockIdx.x * 128;
    const int codeBase = blockIdx.y * 128;

    // ldmatrix lane addressing (within a tile)
    const int q = lane >> 3, i8 = lane & 7;
    const uint32_t aOff = (uint32_t)(((wm * 32 + (q & 1) * 8 + i8) * SB + (q >> 1) * 8) * 2);
    const uint32_t bOff = (uint32_t)(((wn * 64 + (q >> 1) * 8 + i8) * SB + (q & 1) * 8) * 2);

    float acc[2][8][4];
#pragma unroll
    for (int mt = 0; mt < 2; ++mt)
#pragma unroll
        for (int nt = 0; nt < 8; ++nt)
#pragma unroll
            for (int e = 0; e < 4; ++e) acc[mt][nt][e] = 0.f;

    // stage k-chunk kt (32 k) into ring buffer 'buf': 1024 x 16B, 4/thread
    auto stage = [&](int buf, int kt) {
        uint32_t base = smBase + buf * STAGEB;
        int kc = kt * 32;
#pragma unroll
        for (int i = 0; i < 4; ++i) {
            int c = tid + i * 256;              // 0..1023
            int hf = c & 3;
            int r = (c >> 2) & 127;
            int tile = c >> 9;                  // 0=zh, 1=eh
            const __nv_bfloat16* src = (tile == 0) ? g_zh : g_cbh;
            int gr = (tile == 0) ? (rowBase + r) : (codeBase + r);
            cp16(base + (uint32_t)(tile * TILEB + r * (SB * 2) + hf * 16),
                 src + (size_t)gr * D + kc + hf * 8);
        }
        asm volatile("cp.async.commit_group;" ::: "memory");
    };

    stage(0, 0);
    stage(1, 1);
#pragma unroll
    for (int kt = 0; kt < 8; ++kt) {
        int buf = kt - (kt >= 3 ? 3 : 0) - (kt >= 6 ? 3 : 0);   // kt % 3
        if (kt < 7) asm volatile("cp.async.wait_group 1;" ::: "memory");
        else        asm volatile("cp.async.wait_group 0;" ::: "memory");
        __syncthreads();
        if (kt < 6) {
            int nb = kt + 2;
            stage(nb - (nb >= 3 ? 3 : 0) - (nb >= 6 ? 3 : 0), nb);
        }

        uint32_t tb = smBase + buf * STAGEB;
#pragma unroll
        for (int kh = 0; kh < 2; ++kh) {
            uint32_t ah[2][4], bfr[8][2];
#pragma unroll
            for (int mt = 0; mt < 2; ++mt)
                ldsm_x4(ah[mt][0], ah[mt][1], ah[mt][2], ah[mt][3],
                        tb + aOff + (uint32_t)(mt * 16 * SB * 2 + kh * 32));
#pragma unroll
            for (int nt2 = 0; nt2 < 4; ++nt2) {
                uint32_t r0, r1, r2, r3;
                ldsm_x4(r0, r1, r2, r3,
                        tb + TILEB + bOff + (uint32_t)(nt2 * 16 * SB * 2 + kh * 32));
                bfr[nt2 * 2 + 0][0] = r0; bfr[nt2 * 2 + 0][1] = r1;
                bfr[nt2 * 2 + 1][0] = r2; bfr[nt2 * 2 + 1][1] = r3;
            }
#pragma unroll
            for (int mt = 0; mt < 2; ++mt)
#pragma unroll
                for (int nt = 0; nt < 8; ++nt)
                    mma16816(acc[mt][nt], ah[mt][0], ah[mt][1], ah[mt][2], ah[mt][3],
                             bfr[nt][0], bfr[nt][1]);
        }
    }

    // ---- epilogue: d = cn - 2*dot, per-row top-2 over this CTA's 128 codes ----
    __syncthreads();                      // mainloop smem dead; alias as red[]
    float4 (*red)[2] = reinterpret_cast<float4(*)[2]>(smem);

    const int g = lane >> 2;
    const int cb0 = codeBase + wn * 64 + (lane & 3) * 2;
    float cn8[8][2];
#pragma unroll
    for (int nt = 0; nt < 8; ++nt) {
        cn8[nt][0] = __ldg(&g_cn[cb0 + nt * 8 + 0]);
        cn8[nt][1] = __ldg(&g_cn[cb0 + nt * 8 + 1]);
    }
#pragma unroll
    for (int mt = 0; mt < 2; ++mt)
#pragma unroll
        for (int h = 0; h < 2; ++h) {
            float v0 = CUDART_INF_F, v1 = CUDART_INF_F;
            int i0 = 0, i1 = 0;
#pragma unroll
            for (int nt = 0; nt < 8; ++nt)
#pragma unroll
                for (int e = 0; e < 2; ++e) {
                    float dd = fmaf(-2.f, acc[mt][nt][h * 2 + e], cn8[nt][e]);
                    int code = cb0 + nt * 8 + e;
                    if (dd < v0) { v1 = v0; i1 = i0; v0 = dd; i0 = code; }
                    else if (dd < v1) { v1 = dd; i1 = code; }
                }
#pragma unroll
            for (int off = 1; off <= 2; off <<= 1) {
                float w0 = __shfl_xor_sync(0xffffffffu, v0, off);
                float w1 = __shfl_xor_sync(0xffffffffu, v1, off);
                int j0 = __shfl_xor_sync(0xffffffffu, i0, off);
                int j1 = __shfl_xor_sync(0xffffffffu, i1, off);
                top2_merge(v0, i0, v1, i1, w0, j0, w1, j1);
            }
            if ((lane & 3) == 0)
                red[wm * 32 + mt * 16 + h * 8 + g][wn] =
                    make_float4(v0, __int_as_float(i0), v1, __int_as_float(i1));
        }
    __syncthreads();

    if (tid < 128) {
        float4 p0 = red[tid][0];
        float4 p1 = red[tid][1];
        float v0 = p0.x, v1 = p0.z;
        int i0 = __float_as_int(p0.y), i1 = __float_as_int(p0.w);
        top2_merge(v0, i0, v1, i1, p1.x, __float_as_int(p1.y), p1.z, __float_as_int(p1.w));
        size_t slot = (size_t)(rowBase + tid) * gridDim.y + blockIdx.y;
        g_cv[slot] = make_float2(v0, v1);
        g_ci[slot] = make_int2(i0, i1);
    }
}

// ============================================================================
// Kernel 4 (fused): per-row approx top-8 + exact fp32 rescore + gather q into
// out + elementwise loss partial. One warp per row; 8 rows per block.
// ============================================================================
__global__ __launch_bounds__(256)
void rescore_gather_kernel(float* __restrict__ out,
                           const float* __restrict__ cb, int NT) {
    __shared__ float wloss[8];
    int warp = threadIdx.x >> 5;
    int row = blockIdx.x * 8 + warp;
    int lane = threadIdx.x & 31;

    float v[4];
    int ix[4];
#pragma unroll
    for (int k = 0; k < 4; ++k) { v[k] = CUDART_INF_F; ix[k] = 0x7fffffff; }
#pragma unroll
    for (int p = 0; p < 2; ++p) {
        int s = lane + p * 32;
        if (s < NT) {
            float2 cv = g_cv[(size_t)row * NT + s];
            int2 ci = g_ci[(size_t)row * NT + s];
            v[p * 2 + 0] = cv.x; ix[p * 2 + 0] = ci.x;
            v[p * 2 + 1] = cv.y; ix[p * 2 + 1] = ci.y;
        }
    }

    // select approx top-8 (8 rounds of global argmin with consumption)
    int jj[8];
#pragma unroll
    for (int r = 0; r < 8; ++r) {
        float bv = CUDART_INF_F; int bi = 0x7fffffff;
#pragma unroll
        for (int k = 0; k < 4; ++k)
            if (v[k] < bv || (v[k] == bv && ix[k] < bi)) { bv = v[k]; bi = ix[k]; }
#pragma unroll
        for (int off = 16; off > 0; off >>= 1) {
            float wv = __shfl_xor_sync(0xffffffffu, bv, off);
            int wi = __shfl_xor_sync(0xffffffffu, bi, off);
            if (wv < bv || (wv == bv && wi < bi)) { bv = wv; bi = wi; }
        }
        jj[r] = (bi == 0x7fffffff) ? 0 : bi;
#pragma unroll
        for (int k = 0; k < 4; ++k)
            if (ix[k] == bi) { v[k] = CUDART_INF_F; ix[k] = 0x7fffffff; }
    }

    // exact fp32 rescore of 8 candidates: d_j = cn[j] - 2 * z.e_j
    float4* zr = reinterpret_cast<float4*>(out + (size_t)row * D);
    float4 z0 = zr[lane], z1 = zr[lane + 32];
    float s8[8];
#pragma unroll
    for (int j = 0; j < 8; ++j) {
        const float4* ej = reinterpret_cast<const float4*>(cb + (size_t)jj[j] * D);
        float4 a = ej[lane];
        float4 c = ej[lane + 32];
        float s = 0.f;
        s = fmaf(z0.x, a.x, s); s = fmaf(z0.y, a.y, s);
        s = fmaf(z0.z, a.z, s); s = fmaf(z0.w, a.w, s);
        s = fmaf(z1.x, c.x, s); s = fmaf(z1.y, c.y, s);
        s = fmaf(z1.z, c.z, s); s = fmaf(z1.w, c.w, s);
        s8[j] = s;
    }
#pragma unroll
    for (int off = 16; off > 0; off >>= 1) {
#pragma unroll
        for (int j = 0; j < 8; ++j)
            s8[j] += __shfl_xor_sync(0xffffffffu, s8[j], off);
    }
    // every lane has all sums -> identical winner everywhere
    float best = CUDART_INF_F; int bi = 0x7fffffff;
#pragma unroll
    for (int j = 0; j < 8; ++j) {
        float dj = g_cn[jj[j]] - 2.f * s8[j];
        if (dj < best || (dj == best && jj[j] < bi)) { best = dj; bi = jj[j]; }
    }

    // gather q, write x_recon row (= q), accumulate elementwise loss
    const float4* ew = reinterpret_cast<const float4*>(cb + (size_t)bi * D);
    float ls = 0.f;
    {
        float4 qv = ew[lane];
        zr[lane] = qv;
        float dx = z0.x - qv.x, dy = z0.y - qv.y;
        float dz = z0.z - qv.z, dw = z0.w - qv.w;
        ls += dx * dx + dy * dy + dz * dz + dw * dw;
        qv = ew[lane + 32];
        zr[lane + 32] = qv;
        dx = z1.x - qv.x; dy = z1.y - qv.y;
        dz = z1.z - qv.z; dw = z1.w - qv.w;
        ls += dx * dx + dy * dy + dz * dz + dw * dw;
    }
#pragma unroll
    for (int off = 16; off > 0; off >>= 1)
        ls += __shfl_xor_sync(0xffffffffu, ls, off);
    if (lane == 0) wloss[warp] = ls;
    __syncthreads();
    if (threadIdx.x == 0) {
        float t = 0.f;
#pragma unroll
        for (int w = 0; w < 8; ++w) t += wloss[w];
        g_part[blockIdx.x] = t;
    }
}

// ============================================================================
// Kernel 5: finalize losses (4096 partials, deterministic tree)
// ============================================================================
__global__ __launch_bounds__(1024)
void finalize_kernel(float* __restrict__ out, int out_size, float inv_count) {
    __shared__ float sr[1024];
    int t = threadIdx.x;
    float s = 0.f;
#pragma unroll
    for (int p = 0; p < 4; ++p) s += g_part[t + p * 1024];
    sr[t] = s;
    __syncthreads();
    for (int st = 512; st > 0; st >>= 1) {
        if (t < st) sr[t] += sr[t + st];
        __syncthreads();
    }
    if (t == 0) {
        float m = sr[0] * inv_count;
        out[out_size - 2] = m;
        out[out_size - 1] = m;
    }
}

// ============================================================================
extern "C" void kernel_launch(void* const* d_in, const int* in_sizes, int n_in,
                              void* d_out, int out_size) {
    const float* x  = (const float*)d_in[0];
    const float* W  = (const float*)d_in[1];
    const float* b  = (const float*)d_in[2];
    const float* cb = (const float*)d_in[3];

    int M      = in_sizes[0] / D;   // 32768
    int Kcodes = in_sizes[3] / D;   // 8192
    int NT     = Kcodes / 128;      // 64
    float* out = (float*)d_out;

    cudaFuncSetAttribute(dist_mma_kernel,
                         cudaFuncAttributeMaxDynamicSharedMemorySize, DIST_SMEM);

    // 1. fused codebook norms + bf16 hi split
    cnsplit_kernel<<<Kcodes / 8, 256>>>(cb);

    // 2. projection (exact fp32 z into out, plus bf16 hi of z)
    dim3 pg(M / BM, D / BN);
    proj_kernel<<<pg, NTHREADS>>>(x, W, b, out);

    // 3. HMMA distance GEMM (1-term, 128x128 tiles, warp 32x64, 2 CTA/SM)
    dist_mma_kernel<<<dim3(M / 128, NT), 256, DIST_SMEM>>>(Kcodes);

    // 4. fused top-8 select + exact rescore + gather + loss partials
    rescore_gather_kernel<<<M / 8, 256>>>(out, cb, NT);

    // 5. finalize
    finalize_kernel<<<1, 1024>>>(out, out_size, 1.0f / (float)(M * D));
}